// round 1
// baseline (speedup 1.0000x reference)
#include <cuda_runtime.h>
#include <math.h>

#define NNODES 8192
#define MAXDEG 128

// ---------------- scratch (no allocations allowed) ----------------
__device__ float g_Wh1 [NNODES * 200];
__device__ float g_h1  [NNODES * 200];
__device__ float g_h2  [NNODES * 200];
__device__ float g_Wh2a[NNODES * 128];
__device__ float g_Wh2b[NNODES * 128];
__device__ float g_fs1 [NNODES];
__device__ float g_fd1 [NNODES];
__device__ float g_fs2a[NNODES];
__device__ float g_fd2a[NNODES];
__device__ float g_fs2b[NNODES];
__device__ float g_fd2b[NNODES];
__device__ int   g_colA[NNODES * MAXDEG];
__device__ int   g_colT[NNODES * MAXDEG];
__device__ int   g_cntA[NNODES];
__device__ int   g_cntT[NNODES];

// ---------------- kernels ----------------

__global__ void zero_counts_kernel(int* a, int* b) {
    int i = blockIdx.x * blockDim.x + threadIdx.x;
    if (i < NNODES) { a[i] = 0; b[i] = 0; }
}

__device__ __forceinline__ void add_edge(int i, int j, int* cnt, int* col) {
    int p = atomicAdd(&cnt[i], 1);
    if (p < MAXDEG) col[i * MAXDEG + p] = j;
}

// One pass over dense A (as float4): builds row lists of A and of A^T.
__global__ void build_edges_kernel(const float4* __restrict__ A4,
                                   int* cntA, int* colA, int* cntT, int* colT) {
    const long total = (long)NNODES * NNODES / 4;
    for (long v = blockIdx.x * (long)blockDim.x + threadIdx.x; v < total;
         v += (long)gridDim.x * blockDim.x) {
        float4 val = A4[v];
        long base = v * 4;
        int i = (int)(base >> 13);          // row (8192 = 2^13)
        int j0 = (int)(base & 8191);        // col of .x
        if (val.x > 0.f) { add_edge(i, j0    , cntA, colA); add_edge(j0    , i, cntT, colT); }
        if (val.y > 0.f) { add_edge(i, j0 + 1, cntA, colA); add_edge(j0 + 1, i, cntT, colT); }
        if (val.z > 0.f) { add_edge(i, j0 + 2, cntA, colA); add_edge(j0 + 2, i, cntT, colT); }
        if (val.w > 0.f) { add_edge(i, j0 + 3, cntA, colA); add_edge(j0 + 3, i, cntT, colT); }
    }
}

// C[M,Nc] = A[M,K] @ B[K,Nc], fp32, 64x64 tile, 4x4 microtile, 256 threads.
__global__ void sgemm64_kernel(const float* __restrict__ A, const float* __restrict__ B,
                               float* __restrict__ C, int M, int K, int Nc) {
    const int BK = 16;
    __shared__ float As[16][64];
    __shared__ float Bs[16][64];
    int tid = threadIdx.x;
    int tx = tid & 15, ty = tid >> 4;
    int rowBase = blockIdx.y * 64;
    int colBase = blockIdx.x * 64;
    float acc[4][4] = {};
    for (int k0 = 0; k0 < K; k0 += BK) {
#pragma unroll
        for (int l = 0; l < 4; l++) {
            int idx = tid + l * 256;           // 0..1023  (64x16 A tile)
            int m = idx >> 4, kk = idx & 15;
            As[kk][m] = (k0 + kk < K) ? A[(size_t)(rowBase + m) * K + k0 + kk] : 0.f;
        }
#pragma unroll
        for (int l = 0; l < 4; l++) {
            int idx = tid + l * 256;           // 16x64 B tile
            int kk = idx >> 6, n = idx & 63;
            Bs[kk][n] = (k0 + kk < K && colBase + n < Nc)
                            ? B[(size_t)(k0 + kk) * Nc + colBase + n] : 0.f;
        }
        __syncthreads();
#pragma unroll
        for (int kk = 0; kk < BK; kk++) {
            float a[4], b[4];
#pragma unroll
            for (int i = 0; i < 4; i++) a[i] = As[kk][ty * 4 + i];
#pragma unroll
            for (int j = 0; j < 4; j++) b[j] = Bs[kk][tx * 4 + j];
#pragma unroll
            for (int i = 0; i < 4; i++)
#pragma unroll
                for (int j = 0; j < 4; j++) acc[i][j] += a[i] * b[j];
        }
        __syncthreads();
    }
#pragma unroll
    for (int i = 0; i < 4; i++) {
        int r = rowBase + ty * 4 + i;
#pragma unroll
        for (int j = 0; j < 4; j++) {
            int cc = colBase + tx * 4 + j;
            if (cc < Nc) C[(size_t)r * Nc + cc] = acc[i][j];
        }
    }
}

// Per-row dots: fs[i] = Wh[i,:].a_src ; fd[i] = Wh[i,:].a_dst   (warp per row)
__global__ void fsrc_fdst_kernel(const float* __restrict__ Wh,
                                 const float* __restrict__ as_, const float* __restrict__ ad_,
                                 float* __restrict__ fs, float* __restrict__ fd, int F) {
    int row = blockIdx.x * (blockDim.x >> 5) + (threadIdx.x >> 5);
    int lane = threadIdx.x & 31;
    if (row >= NNODES) return;
    const float* w = Wh + (size_t)row * F;
    float s = 0.f, d = 0.f;
    for (int f = lane; f < F; f += 32) { float v = w[f]; s += v * as_[f]; d += v * ad_[f]; }
#pragma unroll
    for (int o = 16; o > 0; o >>= 1) {
        s += __shfl_xor_sync(0xffffffffu, s, o);
        d += __shfl_xor_sync(0xffffffffu, d, o);
    }
    if (lane == 0) { fs[row] = s; fd[row] = d; }
}

// Sparse GAT row: softmax over neighbors, weighted aggregate of Wh, relu.
// Warp per row; neighbor count <= MAXDEG (4 per lane).
template <int F>
__global__ void gat_agg_kernel(const int* __restrict__ col, const int* __restrict__ cnt,
                               const float* __restrict__ fs, const float* __restrict__ fd,
                               const float* __restrict__ Wh,
                               float* __restrict__ outp, int outStride,
                               float* __restrict__ hOut) {
    int row = blockIdx.x * (blockDim.x >> 5) + (threadIdx.x >> 5);
    int lane = threadIdx.x & 31;
    if (row >= NNODES) return;
    int c = cnt[row];
    if (c > MAXDEG) c = MAXDEG;
    constexpr int NF = (F + 31) / 32;
    float acc[NF];
#pragma unroll
    for (int i = 0; i < NF; i++) acc[i] = 0.f;

    if (c > 0) {
        const int* cl = col + (size_t)row * MAXDEG;
        float fsr = fs[row];
        int jv[4];
        float sv[4];
#pragma unroll
        for (int t = 0; t < 4; t++) {
            int idx = lane + t * 32;
            if (idx < c) {
                int j = cl[idx];
                float z = fsr + fd[j];
                sv[t] = z > 0.f ? z : 0.1f * z;   // leaky_relu, alpha=0.1
                jv[t] = j;
            } else { sv[t] = -3.4e38f; jv[t] = 0; }
        }
        float m = fmaxf(fmaxf(sv[0], sv[1]), fmaxf(sv[2], sv[3]));
#pragma unroll
        for (int o = 16; o > 0; o >>= 1) m = fmaxf(m, __shfl_xor_sync(0xffffffffu, m, o));
        float ev[4];
        float zs = 0.f;
#pragma unroll
        for (int t = 0; t < 4; t++) {
            int idx = lane + t * 32;
            float e = (idx < c) ? expf(sv[t] - m) : 0.f;
            ev[t] = e; zs += e;
        }
#pragma unroll
        for (int o = 16; o > 0; o >>= 1) zs += __shfl_xor_sync(0xffffffffu, zs, o);
        float invZ = 1.f / zs;
        for (int idx = 0; idx < c; ++idx) {
            int t = idx >> 5, src = idx & 31;
            int   j = __shfl_sync(0xffffffffu, jv[t], src);
            float p = __shfl_sync(0xffffffffu, ev[t], src) * invZ;
            const float* w = Wh + (size_t)j * F;
#pragma unroll
            for (int ff = 0; ff < NF; ff++) {
                int f = lane + 32 * ff;
                if (f < F) acc[ff] += p * __ldg(w + f);
            }
        }
    } else {
        // empty row: reference softmax over all -9e15 -> uniform 1/N over ALL nodes
        for (int j = 0; j < NNODES; j++) {
            const float* w = Wh + (size_t)j * F;
#pragma unroll
            for (int ff = 0; ff < NF; ff++) {
                int f = lane + 32 * ff;
                if (f < F) acc[ff] += w[f];
            }
        }
#pragma unroll
        for (int ff = 0; ff < NF; ff++) acc[ff] *= (1.f / NNODES);
    }

#pragma unroll
    for (int ff = 0; ff < NF; ff++) {
        int f = lane + 32 * ff;
        if (f < F) {
            float v = fmaxf(acc[ff], 0.f);   // relu
            outp[(size_t)row * outStride + f] = v;
            if (hOut) hOut[(size_t)row * F + f] = v;
        }
    }
}

// ---------------- launch ----------------
extern "C" void kernel_launch(void* const* d_in, const int* in_sizes, int n_in,
                              void* d_out, int out_size) {
    const float* A   = (const float*)d_in[0];
    const float* x   = (const float*)d_in[1];
    const float* W1  = (const float*)d_in[2];
    const float* a1s = (const float*)d_in[3];
    const float* a1d = (const float*)d_in[4];
    const float* W2  = (const float*)d_in[5];
    const float* a2s = (const float*)d_in[6];
    const float* a2d = (const float*)d_in[7];
    float* out = (float*)d_out;

    float *Wh1, *h1, *h2, *Wh2a, *Wh2b;
    float *fs1, *fd1, *fs2a, *fd2a, *fs2b, *fd2b;
    int *colA, *colT, *cntA, *cntT;
    cudaGetSymbolAddress((void**)&Wh1,  g_Wh1);
    cudaGetSymbolAddress((void**)&h1,   g_h1);
    cudaGetSymbolAddress((void**)&h2,   g_h2);
    cudaGetSymbolAddress((void**)&Wh2a, g_Wh2a);
    cudaGetSymbolAddress((void**)&Wh2b, g_Wh2b);
    cudaGetSymbolAddress((void**)&fs1,  g_fs1);
    cudaGetSymbolAddress((void**)&fd1,  g_fd1);
    cudaGetSymbolAddress((void**)&fs2a, g_fs2a);
    cudaGetSymbolAddress((void**)&fd2a, g_fd2a);
    cudaGetSymbolAddress((void**)&fs2b, g_fs2b);
    cudaGetSymbolAddress((void**)&fd2b, g_fd2b);
    cudaGetSymbolAddress((void**)&colA, g_colA);
    cudaGetSymbolAddress((void**)&colT, g_colT);
    cudaGetSymbolAddress((void**)&cntA, g_cntA);
    cudaGetSymbolAddress((void**)&cntT, g_cntT);

    // Output layout: [ x (8192x256) | cat1 (8192x400) | cat2 (8192x256) ]
    float* part1 = out + (size_t)NNODES * 256;
    float* part2 = out + (size_t)NNODES * (256 + 400);

    // 0) copy x to output head
    cudaMemcpyAsync(out, x, (size_t)NNODES * 256 * sizeof(float),
                    cudaMemcpyDeviceToDevice);

    // 1) edge lists for A and A^T (single dense scan)
    zero_counts_kernel<<<32, 256>>>(cntA, cntT);
    build_edges_kernel<<<4096, 256>>>((const float4*)A, cntA, colA, cntT, colT);

    // 2) layer 1: Wh1 = x @ W1  (both branches share it since h1 == h2 == x)
    sgemm64_kernel<<<dim3(4, 128), 256>>>(x, W1, Wh1, NNODES, 256, 200);
    fsrc_fdst_kernel<<<1024, 256>>>(Wh1, a1s, a1d, fs1, fd1, 200);
    gat_agg_kernel<200><<<1024, 256>>>(colA, cntA, fs1, fd1, Wh1, part1,       400, h1);
    gat_agg_kernel<200><<<1024, 256>>>(colT, cntT, fs1, fd1, Wh1, part1 + 200, 400, h2);

    // 3) layer 2: separate Wh per branch
    sgemm64_kernel<<<dim3(2, 128), 256>>>(h1, W2, Wh2a, NNODES, 200, 128);
    sgemm64_kernel<<<dim3(2, 128), 256>>>(h2, W2, Wh2b, NNODES, 200, 128);
    fsrc_fdst_kernel<<<1024, 256>>>(Wh2a, a2s, a2d, fs2a, fd2a, 128);
    fsrc_fdst_kernel<<<1024, 256>>>(Wh2b, a2s, a2d, fs2b, fd2b, 128);
    gat_agg_kernel<128><<<1024, 256>>>(colA, cntA, fs2a, fd2a, Wh2a, part2,       256, nullptr);
    gat_agg_kernel<128><<<1024, 256>>>(colT, cntT, fs2b, fd2b, Wh2b, part2 + 128, 256, nullptr);
}

// round 2
// speedup vs baseline: 1.3253x; 1.3253x over previous
#include <cuda_runtime.h>
#include <math.h>

#define NNODES 8192
#define MAXDEG 128

// ---------------- scratch (no allocations allowed) ----------------
__device__ float g_Wh1[NNODES * 200];
__device__ float g_h  [2 * NNODES * 200];   // [h1 ; h2] contiguous
__device__ float g_Wh2[2 * NNODES * 128];   // [Wh2a ; Wh2b]
__device__ float g_fs1[NNODES];
__device__ float g_fd1[NNODES];
__device__ float g_fs2[2 * NNODES];
__device__ float g_fd2[2 * NNODES];
__device__ int   g_col[2 * NNODES * MAXDEG]; // [colA ; colT]
__device__ int   g_cnt[2 * NNODES];          // [cntA ; cntT]

// ---------------- kernels ----------------

__global__ void zero_counts_kernel(int* c) {
    int i = blockIdx.x * blockDim.x + threadIdx.x;
    if (i < 2 * NNODES) c[i] = 0;
}

__device__ __forceinline__ void add_edge(int i, int j, int* cnt, int* col) {
    int p = atomicAdd(&cnt[i], 1);
    if (p < MAXDEG) col[(size_t)i * MAXDEG + p] = j;
}

// One pass over dense A (float4): builds row lists of A and of A^T.
__global__ void build_edges_kernel(const float4* __restrict__ A4,
                                   int* __restrict__ cnt, int* __restrict__ col) {
    int* cntT = cnt + NNODES;
    int* colT = col + (size_t)NNODES * MAXDEG;
    const long total = (long)NNODES * NNODES / 4;
    for (long v = blockIdx.x * (long)blockDim.x + threadIdx.x; v < total;
         v += (long)gridDim.x * blockDim.x) {
        float4 val = A4[v];
        long base = v * 4;
        int i = (int)(base >> 13);
        int j0 = (int)(base & 8191);
        if (val.x > 0.f) { add_edge(i, j0    , cnt, col); add_edge(j0    , i, cntT, colT); }
        if (val.y > 0.f) { add_edge(i, j0 + 1, cnt, col); add_edge(j0 + 1, i, cntT, colT); }
        if (val.z > 0.f) { add_edge(i, j0 + 2, cnt, col); add_edge(j0 + 2, i, cntT, colT); }
        if (val.w > 0.f) { add_edge(i, j0 + 3, cnt, col); add_edge(j0 + 3, i, cntT, colT); }
    }
}

// C[M,Nc] = A[M,K] @ B[K,Nc] fp32. 128x128 tile, 8x8 micro, BK=8, 256 thr.
// Requires: M % 128 == 0, K % 8 == 0. Nc arbitrary (guarded).
__global__ void sgemm128_kernel(const float* __restrict__ A, const float* __restrict__ B,
                                float* __restrict__ C, int M, int K, int Nc) {
    __shared__ float As[8][128];
    __shared__ float Bs[8][128];
    int tid = threadIdx.x;
    int tx = tid & 15, ty = tid >> 4;
    int rowBase = blockIdx.y * 128;
    int colBase = blockIdx.x * 128;

    int aRow = tid >> 1;          // 0..127
    int aK4  = (tid & 1) * 4;     // 0 or 4
    int bK   = tid >> 5;          // 0..7
    int bN   = (tid & 31) * 4;    // 0..124

    float acc[8][8];
#pragma unroll
    for (int i = 0; i < 8; i++)
#pragma unroll
        for (int j = 0; j < 8; j++) acc[i][j] = 0.f;

    for (int k0 = 0; k0 < K; k0 += 8) {
        float4 av = *(const float4*)(A + (size_t)(rowBase + aRow) * K + k0 + aK4);
        As[aK4 + 0][aRow] = av.x;
        As[aK4 + 1][aRow] = av.y;
        As[aK4 + 2][aRow] = av.z;
        As[aK4 + 3][aRow] = av.w;

        int nIdx = colBase + bN;
        float4 bv;
        const float* brow = B + (size_t)(k0 + bK) * Nc;
        if (nIdx + 3 < Nc) {
            bv = *(const float4*)(brow + nIdx);
        } else {
            bv.x = (nIdx + 0 < Nc) ? brow[nIdx + 0] : 0.f;
            bv.y = (nIdx + 1 < Nc) ? brow[nIdx + 1] : 0.f;
            bv.z = (nIdx + 2 < Nc) ? brow[nIdx + 2] : 0.f;
            bv.w = (nIdx + 3 < Nc) ? brow[nIdx + 3] : 0.f;
        }
        *(float4*)&Bs[bK][bN] = bv;
        __syncthreads();

#pragma unroll
        for (int kk = 0; kk < 8; kk++) {
            float4 a0 = *(const float4*)&As[kk][ty * 8];
            float4 a1 = *(const float4*)&As[kk][ty * 8 + 4];
            float4 b0 = *(const float4*)&Bs[kk][tx * 8];
            float4 b1 = *(const float4*)&Bs[kk][tx * 8 + 4];
            float a[8] = {a0.x, a0.y, a0.z, a0.w, a1.x, a1.y, a1.z, a1.w};
            float b[8] = {b0.x, b0.y, b0.z, b0.w, b1.x, b1.y, b1.z, b1.w};
#pragma unroll
            for (int i = 0; i < 8; i++)
#pragma unroll
                for (int j = 0; j < 8; j++) acc[i][j] = fmaf(a[i], b[j], acc[i][j]);
        }
        __syncthreads();
    }

#pragma unroll
    for (int i = 0; i < 8; i++) {
        int r = rowBase + ty * 8 + i;
        float* crow = C + (size_t)r * Nc;
        int c0 = colBase + tx * 8;
        if (c0 + 7 < Nc) {
            float4 v0 = {acc[i][0], acc[i][1], acc[i][2], acc[i][3]};
            float4 v1 = {acc[i][4], acc[i][5], acc[i][6], acc[i][7]};
            *(float4*)(crow + c0)     = v0;
            *(float4*)(crow + c0 + 4) = v1;
        } else {
#pragma unroll
            for (int j = 0; j < 8; j++)
                if (c0 + j < Nc) crow[c0 + j] = acc[i][j];
        }
    }
}

// Per-row dots (vectorized): fs[i] = Wh[i,:].a_src ; fd[i] = Wh[i,:].a_dst
template <int F>
__global__ void fsrc_fdst_kernel(const float* __restrict__ Wh,
                                 const float* __restrict__ as_, const float* __restrict__ ad_,
                                 float* __restrict__ fs, float* __restrict__ fd, int nRows) {
    constexpr int F4 = F / 4;
    int row = blockIdx.x * 8 + (threadIdx.x >> 5);
    int lane = threadIdx.x & 31;
    if (row >= nRows) return;
    const float4* w4 = (const float4*)(Wh + (size_t)row * F);
    const float4* a4 = (const float4*)as_;
    const float4* d4 = (const float4*)ad_;
    float4 v = __ldg(w4 + lane);
    float4 a = a4[lane];
    float4 d = d4[lane];
    float s = v.x * a.x + v.y * a.y + v.z * a.z + v.w * a.w;
    float t = v.x * d.x + v.y * d.y + v.z * d.z + v.w * d.w;
    if (F4 > 32 && lane < F4 - 32) {
        float4 v2 = __ldg(w4 + 32 + lane);
        float4 a2 = a4[32 + lane];
        float4 d2 = d4[32 + lane];
        s += v2.x * a2.x + v2.y * a2.y + v2.z * a2.z + v2.w * a2.w;
        t += v2.x * d2.x + v2.y * d2.y + v2.z * d2.z + v2.w * d2.w;
    }
#pragma unroll
    for (int o = 16; o > 0; o >>= 1) {
        s += __shfl_xor_sync(0xffffffffu, s, o);
        t += __shfl_xor_sync(0xffffffffu, t, o);
    }
    if (lane == 0) { fs[row] = s; fd[row] = t; }
}

__device__ __forceinline__ float4 f4fma(float p, float4 w, float4 acc) {
    acc.x = fmaf(p, w.x, acc.x);
    acc.y = fmaf(p, w.y, acc.y);
    acc.z = fmaf(p, w.z, acc.z);
    acc.w = fmaf(p, w.w, acc.w);
    return acc;
}

// Sparse GAT row: softmax over neighbors, weighted aggregate of Wh, relu.
// Warp per row. gridDim.y = 2 selects directed branch (A vs A^T).
template <int F>
__global__ void gat_agg_kernel(const int* __restrict__ colB, const int* __restrict__ cntB,
                               const float* __restrict__ fsB, const float* __restrict__ fdB,
                               const float* __restrict__ WhB,
                               float* __restrict__ outB, float* __restrict__ hB,
                               int fsStride, long whStride, int outBranchOff, int outStride,
                               long hStride) {
    constexpr int F4 = F / 4;
    __shared__ float sp[8][MAXDEG];
    __shared__ int   sj[8][MAXDEG];

    int b = blockIdx.y;
    const int* col = colB + (size_t)b * NNODES * MAXDEG;
    const int* cnt = cntB + b * NNODES;
    const float* fs = fsB + (size_t)b * fsStride;
    const float* fd = fdB + (size_t)b * fsStride;
    const float* Wh = WhB + (size_t)b * whStride;
    float* outp = outB + b * outBranchOff;
    float* hOut = hB ? (hB + (size_t)b * hStride) : nullptr;

    int w = threadIdx.x >> 5, lane = threadIdx.x & 31;
    int row = blockIdx.x * 8 + w;
    if (row >= NNODES) return;

    int c = min(cnt[row], MAXDEG);
    float4 acc0 = {0, 0, 0, 0}, acc1 = {0, 0, 0, 0};
    float4 acc0b = {0, 0, 0, 0}, acc1b = {0, 0, 0, 0};

    if (c > 0) {
        const int* cl = col + (size_t)row * MAXDEG;
        float fsr = fs[row];
        int jv[4];
        float sv[4];
#pragma unroll
        for (int t = 0; t < 4; t++) {
            int idx = lane + t * 32;
            if (idx < c) {
                int j = cl[idx];
                float z = fsr + __ldg(fd + j);
                sv[t] = z > 0.f ? z : 0.1f * z;   // leaky_relu alpha=0.1
                jv[t] = j;
            } else { sv[t] = -3.4e38f; jv[t] = 0; }
        }
        float m = fmaxf(fmaxf(sv[0], sv[1]), fmaxf(sv[2], sv[3]));
#pragma unroll
        for (int o = 16; o > 0; o >>= 1) m = fmaxf(m, __shfl_xor_sync(0xffffffffu, m, o));
        float ev[4];
        float zs = 0.f;
#pragma unroll
        for (int t = 0; t < 4; t++) {
            int idx = lane + t * 32;
            float e = (idx < c) ? expf(sv[t] - m) : 0.f;
            ev[t] = e; zs += e;
        }
#pragma unroll
        for (int o = 16; o > 0; o >>= 1) zs += __shfl_xor_sync(0xffffffffu, zs, o);
        float invZ = 1.f / zs;
#pragma unroll
        for (int t = 0; t < 4; t++) {
            int idx = lane + t * 32;
            if (idx < c) { sp[w][idx] = ev[t] * invZ; sj[w][idx] = jv[t]; }
        }
        __syncwarp();

        int idx = 0;
        for (; idx + 1 < c; idx += 2) {
            float p0 = sp[w][idx];     int j0 = sj[w][idx];
            float p1 = sp[w][idx + 1]; int j1 = sj[w][idx + 1];
            const float4* w0 = (const float4*)(Wh + (size_t)j0 * F);
            const float4* w1 = (const float4*)(Wh + (size_t)j1 * F);
            float4 v00 = __ldg(w0 + lane);
            float4 v10 = __ldg(w1 + lane);
            acc0  = f4fma(p0, v00, acc0);
            acc0b = f4fma(p1, v10, acc0b);
            if (F4 > 32 && lane < F4 - 32) {
                float4 v01 = __ldg(w0 + 32 + lane);
                float4 v11 = __ldg(w1 + 32 + lane);
                acc1  = f4fma(p0, v01, acc1);
                acc1b = f4fma(p1, v11, acc1b);
            }
        }
        if (idx < c) {
            float p0 = sp[w][idx]; int j0 = sj[w][idx];
            const float4* w0 = (const float4*)(Wh + (size_t)j0 * F);
            acc0 = f4fma(p0, __ldg(w0 + lane), acc0);
            if (F4 > 32 && lane < F4 - 32)
                acc1 = f4fma(p0, __ldg(w0 + 32 + lane), acc1);
        }
        acc0.x += acc0b.x; acc0.y += acc0b.y; acc0.z += acc0b.z; acc0.w += acc0b.w;
        acc1.x += acc1b.x; acc1.y += acc1b.y; acc1.z += acc1b.z; acc1.w += acc1b.w;
    } else {
        // empty row: reference softmax over all -9e15 -> uniform 1/N over ALL nodes
        for (int j = 0; j < NNODES; j++) {
            const float4* wr = (const float4*)(Wh + (size_t)j * F);
            acc0 = f4fma(1.f, wr[lane], acc0);
            if (F4 > 32 && lane < F4 - 32)
                acc1 = f4fma(1.f, wr[32 + lane], acc1);
        }
        float inv = 1.f / NNODES;
        acc0.x *= inv; acc0.y *= inv; acc0.z *= inv; acc0.w *= inv;
        acc1.x *= inv; acc1.y *= inv; acc1.z *= inv; acc1.w *= inv;
    }

    // relu + store
    float4 r0 = {fmaxf(acc0.x, 0.f), fmaxf(acc0.y, 0.f), fmaxf(acc0.z, 0.f), fmaxf(acc0.w, 0.f)};
    float* orow = outp + (size_t)row * outStride;
    *(float4*)(orow + 4 * lane) = r0;
    if (hOut) *(float4*)(hOut + (size_t)row * F + 4 * lane) = r0;
    if (F4 > 32 && lane < F4 - 32) {
        float4 r1 = {fmaxf(acc1.x, 0.f), fmaxf(acc1.y, 0.f), fmaxf(acc1.z, 0.f), fmaxf(acc1.w, 0.f)};
        *(float4*)(orow + 4 * lane + 128) = r1;
        if (hOut) *(float4*)(hOut + (size_t)row * F + 4 * lane + 128) = r1;
    }
}

// ---------------- launch ----------------
extern "C" void kernel_launch(void* const* d_in, const int* in_sizes, int n_in,
                              void* d_out, int out_size) {
    const float* A   = (const float*)d_in[0];
    const float* x   = (const float*)d_in[1];
    const float* W1  = (const float*)d_in[2];
    const float* a1s = (const float*)d_in[3];
    const float* a1d = (const float*)d_in[4];
    const float* W2  = (const float*)d_in[5];
    const float* a2s = (const float*)d_in[6];
    const float* a2d = (const float*)d_in[7];
    float* out = (float*)d_out;

    float *Wh1, *h, *Wh2, *fs1, *fd1, *fs2, *fd2;
    int *col, *cnt;
    cudaGetSymbolAddress((void**)&Wh1, g_Wh1);
    cudaGetSymbolAddress((void**)&h,   g_h);
    cudaGetSymbolAddress((void**)&Wh2, g_Wh2);
    cudaGetSymbolAddress((void**)&fs1, g_fs1);
    cudaGetSymbolAddress((void**)&fd1, g_fd1);
    cudaGetSymbolAddress((void**)&fs2, g_fs2);
    cudaGetSymbolAddress((void**)&fd2, g_fd2);
    cudaGetSymbolAddress((void**)&col, g_col);
    cudaGetSymbolAddress((void**)&cnt, g_cnt);

    // Output layout: [ x (8192x256) | cat1 (8192x400) | cat2 (8192x256) ]
    float* part1 = out + (size_t)NNODES * 256;
    float* part2 = out + (size_t)NNODES * (256 + 400);

    cudaMemcpyAsync(out, x, (size_t)NNODES * 256 * sizeof(float),
                    cudaMemcpyDeviceToDevice);

    // 1) edge lists for A and A^T (single dense scan)
    zero_counts_kernel<<<64, 256>>>(cnt);
    build_edges_kernel<<<4096, 256>>>((const float4*)A, cnt, col);

    // 2) layer 1
    sgemm128_kernel<<<dim3(2, 64), 256>>>(x, W1, Wh1, NNODES, 256, 200);
    fsrc_fdst_kernel<200><<<1024, 256>>>(Wh1, a1s, a1d, fs1, fd1, NNODES);
    gat_agg_kernel<200><<<dim3(1024, 2), 256>>>(
        col, cnt, fs1, fd1, Wh1, part1, h,
        /*fsStride=*/0, /*whStride=*/0, /*outBranchOff=*/200, /*outStride=*/400,
        /*hStride=*/(long)NNODES * 200);

    // 3) layer 2 (both branches fused: h = [h1;h2] is 16384 x 200)
    sgemm128_kernel<<<dim3(1, 128), 256>>>(h, W2, Wh2, 2 * NNODES, 200, 128);
    fsrc_fdst_kernel<128><<<2048, 256>>>(Wh2, a2s, a2d, fs2, fd2, 2 * NNODES);
    gat_agg_kernel<128><<<dim3(1024, 2), 256>>>(
        col, cnt, fs2, fd2, Wh2, part2, nullptr,
        /*fsStride=*/NNODES, /*whStride=*/(long)NNODES * 128, /*outBranchOff=*/128,
        /*outStride=*/256, /*hStride=*/0);
}